// round 6
// baseline (speedup 1.0000x reference)
#include <cuda_runtime.h>
#include <math.h>

#define MAXM 64
#define PI_180 0.017453292519943295f
#define LN2F   0.6931471805599453f
#define MAXPART 8192

__device__ float g_pc[MAXPART];
__device__ float g_pr[MAXPART];
__device__ float g_pn[MAXPART];
__device__ unsigned int g_count = 0;

struct F2 { float x, y; };

// Faithful port of reference quad_iou (Sutherland-Hodgman clip, MAXV=8).
__device__ float quad_iou(const F2 q1[4], F2 q2[4]) {
    float sa2 = 0.f;
#pragma unroll
    for (int i = 0; i < 4; i++) {
        int j = (i + 1) & 3;
        sa2 += q2[i].x * q2[j].y - q2[i].y * q2[j].x;
    }
    sa2 *= 0.5f;
    if (sa2 < 0.f) {
        F2 t = q2[0]; q2[0] = q2[3]; q2[3] = t;
        t = q2[1]; q2[1] = q2[2]; q2[2] = t;
    }

    F2 pts[8];
    int n = 4;
#pragma unroll
    for (int i = 0; i < 4; i++) pts[i] = q1[i];

#pragma unroll
    for (int k = 0; k < 4; k++) {
        F2 p1 = q2[k];
        F2 p2 = q2[(k + 1) & 3];
        float dx = p2.x - p1.x, dy = p2.y - p1.y;
        F2 out[8];
        int m = 0;
        int nn = n;
        for (int i = 0; i < 8; i++) {
            if (i >= nn) break;
            F2 cur = pts[i];
            F2 nxt = pts[(i + 1 == nn) ? 0 : i + 1];
            float sc = dx * (cur.y - p1.y) - dy * (cur.x - p1.x);
            float sn = dx * (nxt.y - p1.y) - dy * (nxt.x - p1.x);
            bool inc = (sc >= 0.f), inn = (sn >= 0.f);
            if (inc && m < 8) out[m++] = cur;
            if ((inc != inn) && m < 8) {
                float den = sc - sn;
                float t = sc / ((den == 0.f) ? 1.f : den);
                F2 ip;
                ip.x = cur.x + t * (nxt.x - cur.x);
                ip.y = cur.y + t * (nxt.y - cur.y);
                out[m++] = ip;
            }
        }
        n = m;
        for (int i = 0; i < m; i++) pts[i] = out[i];
    }

    float s = 0.f;
    for (int i = 0; i < 8; i++) {
        if (i >= n) break;
        int j = (i + 1 == n) ? 0 : i + 1;
        s += pts[i].x * pts[j].y - pts[i].y * pts[j].x;
    }
    float inter = 0.5f * fabsf(s);

    float sa1 = 0.f;
#pragma unroll
    for (int i = 0; i < 4; i++) {
        int j = (i + 1) & 3;
        sa1 += q1[i].x * q1[j].y - q1[i].y * q1[j].x;
    }
    float a1 = fabsf(0.5f * sa1);
    float a2 = fabsf(sa2);
    return inter / fmaxf(a1 + a2 - inter, 1e-8f);
}

template<int M_T, int NC_T>
__global__ void __launch_bounds__(256, 5)
focal_main_kernel(const float* __restrict__ cls,
                  const float* __restrict__ reg,
                  const float* __restrict__ anch,
                  const float* __restrict__ ann,
                  float* __restrict__ out,
                  int A, int NC_rt, int M_rt)
{
    const int M  = M_T  ? M_T  : M_rt;
    const int NC = NC_T ? NC_T : NC_rt;
    const int b  = blockIdx.y;

    __shared__ float4 s_box[MAXM];
    __shared__ float  s_area[MAXM];
    __shared__ float  s_gpx[MAXM][4];
    __shared__ float  s_gpy[MAXM][4];
    __shared__ float  s_ann[MAXM][6];
    __shared__ float  s_cls[8 * 480];
    __shared__ float  s_anch[8 * 160];
    __shared__ unsigned short s_list[256];
    __shared__ unsigned char  s_harg[256];
    __shared__ unsigned char  s_pos[256];
    __shared__ int    s_cnt;

    if (threadIdx.x == 0) s_cnt = 0;

    for (int j = threadIdx.x; j < M; j += blockDim.x) {
        const float* ar = ann + ((size_t)b * M + j) * 6;
        float a0 = ar[0], a1 = ar[1], a2 = ar[2], a3 = ar[3], a4 = ar[4], a5 = ar[5];
        s_ann[j][0] = a0; s_ann[j][1] = a1; s_ann[j][2] = a2;
        s_ann[j][3] = a3; s_ann[j][4] = a4; s_ann[j][5] = a5;

        float t = a4 * PI_180;
        float sa = sinf(t) * 0.5f;
        float cb = cosf(t) * 0.5f;
        float p0x = a0 - sa * a3 - cb * a2;
        float p0y = a1 + cb * a3 - sa * a2;
        float p1x = a0 + sa * a3 - cb * a2;
        float p1y = a1 - cb * a3 - sa * a2;
        float p2x = 2.f * a0 - p0x;
        float p2y = 2.f * a1 - p0y;
        float p3x = 2.f * a0 - p1x;
        float p3y = 2.f * a1 - p1y;
        s_gpx[j][0] = p0x; s_gpx[j][1] = p1x; s_gpx[j][2] = p2x; s_gpx[j][3] = p3x;
        s_gpy[j][0] = p0y; s_gpy[j][1] = p1y; s_gpy[j][2] = p2y; s_gpy[j][3] = p3y;

        bool valid = (a5 != -1.0f);
        float hx1 = fminf(fminf(p0x, p1x), fminf(p2x, p3x));
        float hx2 = fmaxf(fmaxf(p0x, p1x), fmaxf(p2x, p3x));
        float hy1 = fminf(fminf(p0y, p1y), fminf(p2y, p3y));
        float hy2 = fmaxf(fmaxf(p0y, p1y), fmaxf(p2y, p3y));
        if (!valid) { hx1 = hx2 = hy1 = hy2 = 1e8f; }
        s_box[j]  = make_float4(hx1, hy1, hx2, hy2);
        s_area[j] = (hx2 - hx1) * (hy2 - hy1);
    }

    const int a    = blockIdx.x * blockDim.x + threadIdx.x;
    const int warp = threadIdx.x >> 5;
    const int lane = threadIdx.x & 31;

    // ---- warp-cooperative staging of cls + anchor rows into shared ----
    {
        int a0 = (blockIdx.x * blockDim.x) + (warp << 5);
        if (a0 < A) {
            if (NC_T != 0) {
                size_t base = ((size_t)b * A + a0) * (size_t)NC;
                int maxf = (A - a0) * NC;
                if (maxf > 32 * NC) maxf = 32 * NC;
                float* dstw = s_cls + warp * 480;
                if (maxf == 32 * NC && ((base & 3) == 0)) {
                    const float4* src4 = (const float4*)(cls + base);
                    float4* dst4 = (float4*)dstw;
#pragma unroll
                    for (int i = 0; i < 4; i++) {
                        int idx = lane + i * 32;
                        if (idx < 8 * NC) dst4[idx] = src4[idx];
                    }
                } else {
                    const float* src = cls + base;
                    for (int idx = lane; idx < maxf; idx += 32) dstw[idx] = src[idx];
                }
            }
            size_t abase = (size_t)a0 * 5;
            int maxa = (A - a0) * 5;
            if (maxa > 160) maxa = 160;
            float* dsta = s_anch + warp * 160;
            if (maxa == 160 && ((abase & 3) == 0)) {
                const float4* src4 = (const float4*)(anch + abase);
                float4* dst4 = (float4*)dsta;
#pragma unroll
                for (int i = 0; i < 2; i++) {
                    int idx = lane + i * 32;
                    if (idx < 40) dst4[idx] = src4[idx];
                }
            } else {
                const float* src = anch + abase;
                for (int idx = lane; idx < maxa; idx += 32) dsta[idx] = src[idx];
            }
        }
    }
    __syncthreads();

    float closs = 0.f;   // accumulated in log2-space; scaled by ln2 at the end
    float rsum  = 0.f;
    float isPos = 0.f;

    // ---- phase 1: HBB IoU max (dual independent chains, no argmax) ----
    const float* arow = s_anch + warp * 160 + lane * 5;
    float ax1 = arow[0], ay1 = arow[1], ax2 = arow[2], ay2 = arow[3], ath = arow[4];
    float aw = ax2 - ax1;
    float ah = ay2 - ay1;
    float acx = ax1 + 0.5f * aw;
    float acy = ay1 + 0.5f * ah;
    float aArea = aw * ah;

    float hmax;
    if (M_T != 0) {
        float bi0 = -1.f, bu0 = 1.f;
        float bi1 = -1.f, bu1 = 1.f;
#pragma unroll
        for (int j = 0; j < M_T; j += 2) {
            {
                float4 bb = s_box[j];
                float iw = fmaxf(fminf(ax2, bb.z) - fmaxf(ax1, bb.x), 0.f);
                float ih = fmaxf(fminf(ay2, bb.w) - fmaxf(ay1, bb.y), 0.f);
                float inter = iw * ih;
                float ua = fmaxf(aArea + s_area[j] - inter, 1e-8f);
                if (inter * bu0 > bi0 * ua) { bi0 = inter; bu0 = ua; }
            }
            {
                float4 bb = s_box[j + 1];
                float iw = fmaxf(fminf(ax2, bb.z) - fmaxf(ax1, bb.x), 0.f);
                float ih = fmaxf(fminf(ay2, bb.w) - fmaxf(ay1, bb.y), 0.f);
                float inter = iw * ih;
                float ua = fmaxf(aArea + s_area[j + 1] - inter, 1e-8f);
                if (inter * bu1 > bi1 * ua) { bi1 = inter; bu1 = ua; }
            }
        }
        float num = bi0, den = bu0;
        if (bi1 * bu0 > bi0 * bu1) { num = bi1; den = bu1; }
        hmax = num / den;
    } else {
        float bi = -1.f, bu = 1.f;
        for (int j = 0; j < M; j++) {
            float4 bb = s_box[j];
            float iw = fmaxf(fminf(ax2, bb.z) - fmaxf(ax1, bb.x), 0.f);
            float ih = fmaxf(fminf(ay2, bb.w) - fmaxf(ay1, bb.y), 0.f);
            float inter = iw * ih;
            float ua = fmaxf(aArea + s_area[j] - inter, 1e-8f);
            if (inter * bu > bi * ua) { bi = inter; bu = ua; }
        }
        hmax = bi / bu;
    }

    bool act  = (a < A);
    bool hpos = act && (hmax >= 0.6f);
    bool neg  = act && (hmax < 0.4f);

    // ---- compaction of hpos candidates ----
    {
        unsigned bal = __ballot_sync(0xffffffffu, hpos);
        int cnt_w = __popc(bal);
        int base = 0;
        if (lane == 0 && cnt_w) base = atomicAdd(&s_cnt, cnt_w);
        base = __shfl_sync(0xffffffffu, base, 0);
        if (hpos) {
            int rank = __popc(bal & ((1u << lane) - 1u));
            s_list[base + rank] = (unsigned short)threadIdx.x;
        }
    }

    // ---- neg-branch focal loss (dense, most common) ----
    const float* crow = (NC_T != 0) ? (s_cls + warp * 480 + lane * NC)
                                    : (cls + ((size_t)b * A + (size_t)a) * NC);
    if (neg) {
#pragma unroll
        for (int k = 0; k < (NC_T ? NC_T : 32); k++) {
            if (NC_T == 0 && k >= NC) break;
            float p = fminf(fmaxf(crow[k], 1e-4f), 1.f - 1e-4f);
            closs += 0.75f * p * p * (-__log2f(1.f - p));
        }
    }
    __syncthreads();

    // ---- phase 2: argmax recompute + quad_iou for compacted candidates ----
    int cnt = s_cnt;
    for (int i = threadIdx.x; i < cnt; i += blockDim.x) {
        int t = s_list[i];
        int tw = t >> 5, tl = t & 31;
        const float* trow = s_anch + tw * 160 + tl * 5;
        float tx1 = trow[0], ty1 = trow[1], tx2 = trow[2], ty2 = trow[3];
        float tArea = (tx2 - tx1) * (ty2 - ty1);

        // exact single-chain argmax (same rule as validated kernels)
        float cbi = -1.f, cbu = 1.f;
        int hg = 0;
#pragma unroll
        for (int j = 0; j < (M_T ? M_T : MAXM); j++) {
            if (M_T == 0 && j >= M) break;
            float4 bb = s_box[j];
            float iw = fmaxf(fminf(tx2, bb.z) - fmaxf(tx1, bb.x), 0.f);
            float ih = fmaxf(fminf(ty2, bb.w) - fmaxf(ty1, bb.y), 0.f);
            float inter = iw * ih;
            float ua = fmaxf(tArea + s_area[j] - inter, 1e-8f);
            if (inter * cbu > cbi * ua) { cbi = inter; cbu = ua; hg = j; }
        }
        s_harg[t] = (unsigned char)hg;

        F2 q1[4], q2[4];
#pragma unroll
        for (int c = 0; c < 4; c++) {
            q1[c].x = s_gpx[hg][c];
            q1[c].y = s_gpy[hg][c];
        }
        q2[0].x = tx1; q2[0].y = ty1;
        q2[1].x = tx2; q2[1].y = ty1;
        q2[2].x = tx2; q2[2].y = ty2;
        q2[3].x = tx1; q2[3].y = ty2;
        s_pos[t] = (quad_iou(q1, q2) >= 0.3f) ? 1 : 0;
    }
    __syncthreads();

    // ---- phase 3: pos-branch losses ----
    if (hpos && s_pos[threadIdx.x]) {
        isPos = 1.f;
        int harg = s_harg[threadIdx.x];
        int tc = (int)s_ann[harg][5];
#pragma unroll
        for (int k = 0; k < (NC_T ? NC_T : 32); k++) {
            if (NC_T == 0 && k >= NC) break;
            float p = fminf(fmaxf(crow[k], 1e-4f), 1.f - 1e-4f);
            if (k == tc) {
                float q = 1.f - p;
                closs += 0.25f * q * q * (-__log2f(p));
            } else {
                closs += 0.75f * p * p * (-__log2f(1.f - p));
            }
        }
        float gw = fmaxf(s_ann[harg][2], 1.f);
        float gh = fmaxf(s_ann[harg][3], 1.f);
        float t5[5];
        t5[0] = ((s_ann[harg][0] - acx) / aw) * 10.f;
        t5[1] = ((s_ann[harg][1] - acy) / ah) * 10.f;
        t5[2] = __logf(gw / aw) * 5.f;
        t5[3] = __logf(gh / ah) * 5.f;
        t5[4] = ((s_ann[harg][4] - ath) * PI_180) * 10.f;
        const float* rrow = reg + ((size_t)b * A + a) * 5;
#pragma unroll
        for (int k = 0; k < 5; k++) {
            float d = fabsf(t5[k] - rrow[k]);
            rsum += (d <= (1.f / 9.f)) ? 4.5f * d * d : (d - (0.5f / 9.f));
        }
    }

    closs *= LN2F;   // convert log2-space accumulation back to natural log

    // ---- block reduction ----
    unsigned fullm = 0xffffffffu;
#pragma unroll
    for (int o = 16; o > 0; o >>= 1) {
        closs += __shfl_down_sync(fullm, closs, o);
        rsum  += __shfl_down_sync(fullm, rsum,  o);
        isPos += __shfl_down_sync(fullm, isPos, o);
    }
    __shared__ float red_c[8];
    __shared__ float red_r[8];
    __shared__ float red_p[8];
    if (lane == 0) { red_c[warp] = closs; red_r[warp] = rsum; red_p[warp] = isPos; }
    __syncthreads();

    __shared__ unsigned s_isLast;
    const int nblk = gridDim.x;
    if (threadIdx.x == 0) {
        float tc = 0.f, tr = 0.f, tp = 0.f;
        int nw = blockDim.x >> 5;
        for (int w = 0; w < nw; w++) { tc += red_c[w]; tr += red_r[w]; tp += red_p[w]; }
        int pidx = b * nblk + blockIdx.x;
        g_pc[pidx] = tc;
        g_pr[pidx] = tr;
        g_pn[pidx] = tp;
        __threadfence();
        unsigned total = gridDim.x * gridDim.y;
        unsigned old = atomicAdd(&g_count, 1u);
        s_isLast = (old == total - 1u) ? 1u : 0u;
    }
    __syncthreads();

    if (s_isLast) {
        const int B = gridDim.y;
        int w = warp;
        __shared__ float s_c[8], s_r[8];
        if (w < B) {
            float tc = 0.f, tr = 0.f, tp = 0.f;
            for (int i = lane; i < nblk; i += 32) {
                tc += __ldcg(&g_pc[w * nblk + i]);
                tr += __ldcg(&g_pr[w * nblk + i]);
                tp += __ldcg(&g_pn[w * nblk + i]);
            }
#pragma unroll
            for (int o = 16; o > 0; o >>= 1) {
                tc += __shfl_down_sync(0xffffffffu, tc, o);
                tr += __shfl_down_sync(0xffffffffu, tr, o);
                tp += __shfl_down_sync(0xffffffffu, tp, o);
            }
            if (lane == 0) {
                s_c[w] = tc / fmaxf(tp, 1.f);
                s_r[w] = (tp > 0.f) ? (tr / fmaxf(tp * 5.f, 1.f)) : 0.f;
            }
        }
        __syncthreads();
        if (threadIdx.x == 0) {
            float cm = 0.f, rm = 0.f;
            for (int bb = 0; bb < B; bb++) { cm += s_c[bb]; rm += s_r[bb]; }
            out[0] = cm / (float)B;
            out[1] = rm / (float)B;
            g_count = 0;
        }
    }
}

extern "C" void kernel_launch(void* const* d_in, const int* in_sizes, int n_in,
                              void* d_out, int out_size) {
    const float* cls  = (const float*)d_in[0];
    const float* reg  = (const float*)d_in[1];
    const float* anch = (const float*)d_in[2];
    const float* ann  = (const float*)d_in[3];
    float* out = (float*)d_out;

    int A  = in_sizes[2] / 5;
    int B  = in_sizes[1] / (A * 5);
    int NC = in_sizes[0] / (B * A);
    int M  = in_sizes[3] / (B * 6);
    if (M > MAXM) M = MAXM;

    int nblk = (A + 255) / 256;
    dim3 grid(nblk, B);
    if (M == 32 && NC == 15) {
        focal_main_kernel<32, 15><<<grid, 256>>>(cls, reg, anch, ann, out, A, NC, M);
    } else {
        focal_main_kernel<0, 0><<<grid, 256>>>(cls, reg, anch, ann, out, A, NC, M);
    }
}

// round 7
// speedup vs baseline: 1.5386x; 1.5386x over previous
#include <cuda_runtime.h>
#include <math.h>

#define MAXM 64
#define PI_180 0.017453292519943295f
#define LN2F   0.6931471805599453f
#define MAXPART 8192

__device__ float g_pc[MAXPART];
__device__ float g_pr[MAXPART];
__device__ float g_pn[MAXPART];
__device__ unsigned int g_count = 0;

struct F2 { float x, y; };

// Clip polygon in[0..n) by half-plane  SGN*(coord_AXIS - C) >= 0.
// Faithful to reference Sutherland-Hodgman (incl. den==0 -> t=sc, m<8 cap).
template<int AXIS, int SGN>
__device__ __forceinline__ int clip_axis(const F2* in, int n, float C, F2* out) {
    int m = 0;
    for (int i = 0; i < 8; i++) {
        if (i >= n) break;
        F2 cur = in[i];
        F2 nxt = in[(i + 1 == n) ? 0 : i + 1];
        float sc = (AXIS == 0) ? (cur.x - C) : (cur.y - C);
        float sn = (AXIS == 0) ? (nxt.x - C) : (nxt.y - C);
        if (SGN < 0) { sc = -sc; sn = -sn; }
        bool inc = (sc >= 0.f), inn = (sn >= 0.f);
        if (inc && m < 8) out[m++] = cur;
        if ((inc != inn) && m < 8) {
            float den = sc - sn;
            float t = sc / ((den == 0.f) ? 1.f : den);
            out[m].x = cur.x + t * (nxt.x - cur.x);
            out[m].y = cur.y + t * (nxt.y - cur.y);
            m++;
        }
    }
    return m;
}

// IoU of gt quad q1 vs axis-aligned anchor rect [x1,x2]x[y1,y2].
__device__ float quad_rect_iou(const F2 q1[4],
                               float x1, float y1, float x2, float y2) {
    F2 pa[8], pb[8];
#pragma unroll
    for (int i = 0; i < 4; i++) pa[i] = q1[i];
    int n = 4;
    n = clip_axis<1, +1>(pa, n, y1, pb);   // keep q.y >= y1
    n = clip_axis<0, -1>(pb, n, x2, pa);   // keep q.x <= x2
    n = clip_axis<1, -1>(pa, n, y2, pb);   // keep q.y <= y2
    n = clip_axis<0, +1>(pb, n, x1, pa);   // keep q.x >= x1

    float s = 0.f;
    for (int i = 0; i < 8; i++) {
        if (i >= n) break;
        int j = (i + 1 == n) ? 0 : i + 1;
        s += pa[i].x * pa[j].y - pa[i].y * pa[j].x;
    }
    float inter = 0.5f * fabsf(s);

    float sa1 = 0.f;
#pragma unroll
    for (int i = 0; i < 4; i++) {
        int j = (i + 1) & 3;
        sa1 += q1[i].x * q1[j].y - q1[i].y * q1[j].x;
    }
    float a1 = fabsf(0.5f * sa1);
    float a2 = (x2 - x1) * (y2 - y1);
    return inter / fmaxf(a1 + a2 - inter, 1e-8f);
}

template<int M_T, int NC_T>
__global__ void __launch_bounds__(256)
focal_main_kernel(const float* __restrict__ cls,
                  const float* __restrict__ reg,
                  const float* __restrict__ anch,
                  const float* __restrict__ ann,
                  float* __restrict__ out,
                  int A, int NC_rt, int M_rt)
{
    const int M  = M_T  ? M_T  : M_rt;
    const int NC = NC_T ? NC_T : NC_rt;
    const int b  = blockIdx.y;

    __shared__ float4 s_box[MAXM];
    __shared__ float  s_area[MAXM];
    __shared__ float  s_gpx[MAXM][4];
    __shared__ float  s_gpy[MAXM][4];
    __shared__ float  s_ann[MAXM][6];
    __shared__ float  s_cls[8 * 480];
    __shared__ float  s_anch[8 * 160];
    __shared__ unsigned short s_list[256];
    __shared__ unsigned char  s_harg[256];
    __shared__ unsigned char  s_pos[256];
    __shared__ int    s_cnt;

    if (threadIdx.x == 0) s_cnt = 0;

    for (int j = threadIdx.x; j < M; j += blockDim.x) {
        const float* ar = ann + ((size_t)b * M + j) * 6;
        float a0 = ar[0], a1 = ar[1], a2 = ar[2], a3 = ar[3], a4 = ar[4], a5 = ar[5];
        s_ann[j][0] = a0; s_ann[j][1] = a1; s_ann[j][2] = a2;
        s_ann[j][3] = a3; s_ann[j][4] = a4; s_ann[j][5] = a5;

        float t = a4 * PI_180;
        float sa = sinf(t) * 0.5f;
        float cb = cosf(t) * 0.5f;
        float p0x = a0 - sa * a3 - cb * a2;
        float p0y = a1 + cb * a3 - sa * a2;
        float p1x = a0 + sa * a3 - cb * a2;
        float p1y = a1 - cb * a3 - sa * a2;
        float p2x = 2.f * a0 - p0x;
        float p2y = 2.f * a1 - p0y;
        float p3x = 2.f * a0 - p1x;
        float p3y = 2.f * a1 - p1y;
        s_gpx[j][0] = p0x; s_gpx[j][1] = p1x; s_gpx[j][2] = p2x; s_gpx[j][3] = p3x;
        s_gpy[j][0] = p0y; s_gpy[j][1] = p1y; s_gpy[j][2] = p2y; s_gpy[j][3] = p3y;

        bool valid = (a5 != -1.0f);
        float hx1 = fminf(fminf(p0x, p1x), fminf(p2x, p3x));
        float hx2 = fmaxf(fmaxf(p0x, p1x), fmaxf(p2x, p3x));
        float hy1 = fminf(fminf(p0y, p1y), fminf(p2y, p3y));
        float hy2 = fmaxf(fmaxf(p0y, p1y), fmaxf(p2y, p3y));
        if (!valid) { hx1 = hx2 = hy1 = hy2 = 1e8f; }
        s_box[j]  = make_float4(hx1, hy1, hx2, hy2);
        s_area[j] = (hx2 - hx1) * (hy2 - hy1);
    }

    const int a    = blockIdx.x * blockDim.x + threadIdx.x;
    const int warp = threadIdx.x >> 5;
    const int lane = threadIdx.x & 31;

    // ---- warp-cooperative staging of cls + anchor rows into shared ----
    {
        int a0 = (blockIdx.x * blockDim.x) + (warp << 5);
        if (a0 < A) {
            if (NC_T != 0) {
                size_t base = ((size_t)b * A + a0) * (size_t)NC;
                int maxf = (A - a0) * NC;
                if (maxf > 32 * NC) maxf = 32 * NC;
                float* dstw = s_cls + warp * 480;
                if (maxf == 32 * NC && ((base & 3) == 0)) {
                    const float4* src4 = (const float4*)(cls + base);
                    float4* dst4 = (float4*)dstw;
#pragma unroll
                    for (int i = 0; i < 4; i++) {
                        int idx = lane + i * 32;
                        if (idx < 8 * NC) dst4[idx] = src4[idx];
                    }
                } else {
                    const float* src = cls + base;
                    for (int idx = lane; idx < maxf; idx += 32) dstw[idx] = src[idx];
                }
            }
            size_t abase = (size_t)a0 * 5;
            int maxa = (A - a0) * 5;
            if (maxa > 160) maxa = 160;
            float* dsta = s_anch + warp * 160;
            if (maxa == 160 && ((abase & 3) == 0)) {
                const float4* src4 = (const float4*)(anch + abase);
                float4* dst4 = (float4*)dsta;
#pragma unroll
                for (int i = 0; i < 2; i++) {
                    int idx = lane + i * 32;
                    if (idx < 40) dst4[idx] = src4[idx];
                }
            } else {
                const float* src = anch + abase;
                for (int idx = lane; idx < maxa; idx += 32) dsta[idx] = src[idx];
            }
        }
    }
    __syncthreads();

    float closs = 0.f;   // log2-space accumulation; scaled by ln2 at the end
    float rsum  = 0.f;
    float isPos = 0.f;

    // ---- phase 1: HBB IoU argmax (single chain, no ua clamp) ----
    const float* arow = s_anch + warp * 160 + lane * 5;
    float ax1 = arow[0], ay1 = arow[1], ax2 = arow[2], ay2 = arow[3], ath = arow[4];
    float aw = ax2 - ax1;
    float ah = ay2 - ay1;
    float acx = ax1 + 0.5f * aw;
    float acy = ay1 + 0.5f * ah;
    float aArea = aw * ah;

    float bi = -1.f, bu = 1.f;
    int   harg = 0;
#pragma unroll
    for (int j = 0; j < (M_T ? M_T : MAXM); j++) {
        if (M_T == 0 && j >= M) break;
        float4 bb = s_box[j];
        float iw = fmaxf(fminf(ax2, bb.z) - fmaxf(ax1, bb.x), 0.f);
        float ih = fmaxf(fminf(ay2, bb.w) - fmaxf(ay1, bb.y), 0.f);
        float inter = iw * ih;
        float ua = aArea + s_area[j] - inter;   // ua >= aArea > 0 always
        if (inter * bu > bi * ua) { bi = inter; bu = ua; harg = j; }
    }
    float hmax = bi / bu;   // exact IEEE division, reference rounding

    bool act  = (a < A);
    bool hpos = act && (hmax >= 0.6f);
    bool neg  = act && (hmax < 0.4f);
    s_harg[threadIdx.x] = (unsigned char)harg;

    // ---- compaction of hpos candidates ----
    {
        unsigned bal = __ballot_sync(0xffffffffu, hpos);
        int cnt_w = __popc(bal);
        int base = 0;
        if (lane == 0 && cnt_w) base = atomicAdd(&s_cnt, cnt_w);
        base = __shfl_sync(0xffffffffu, base, 0);
        if (hpos) {
            int rank = __popc(bal & ((1u << lane) - 1u));
            s_list[base + rank] = (unsigned short)threadIdx.x;
        }
    }

    // ---- neg-branch focal loss (dense, most common) ----
    const float* crow = (NC_T != 0) ? (s_cls + warp * 480 + lane * NC)
                                    : (cls + ((size_t)b * A + (size_t)a) * NC);
    if (neg) {
#pragma unroll
        for (int k = 0; k < (NC_T ? NC_T : 32); k++) {
            if (NC_T == 0 && k >= NC) break;
            float p = fminf(fmaxf(crow[k], 1e-4f), 1.f - 1e-4f);
            closs += 0.75f * p * p * (-__log2f(1.f - p));
        }
    }
    __syncthreads();

    // ---- phase 2: dense quad-vs-rect IoU over compacted candidates ----
    int cnt = s_cnt;
    for (int i = threadIdx.x; i < cnt; i += blockDim.x) {
        int t = s_list[i];
        int tw = t >> 5, tl = t & 31;
        const float* trow = s_anch + tw * 160 + tl * 5;
        float tx1 = trow[0], ty1 = trow[1], tx2 = trow[2], ty2 = trow[3];
        int hg = s_harg[t];
        F2 q1[4];
#pragma unroll
        for (int c = 0; c < 4; c++) {
            q1[c].x = s_gpx[hg][c];
            q1[c].y = s_gpy[hg][c];
        }
        s_pos[t] = (quad_rect_iou(q1, tx1, ty1, tx2, ty2) >= 0.3f) ? 1 : 0;
    }
    __syncthreads();

    // ---- phase 3: pos-branch losses ----
    if (hpos && s_pos[threadIdx.x]) {
        isPos = 1.f;
        int tc = (int)s_ann[harg][5];
#pragma unroll
        for (int k = 0; k < (NC_T ? NC_T : 32); k++) {
            if (NC_T == 0 && k >= NC) break;
            float p = fminf(fmaxf(crow[k], 1e-4f), 1.f - 1e-4f);
            if (k == tc) {
                float q = 1.f - p;
                closs += 0.25f * q * q * (-__log2f(p));
            } else {
                closs += 0.75f * p * p * (-__log2f(1.f - p));
            }
        }
        float gw = fmaxf(s_ann[harg][2], 1.f);
        float gh = fmaxf(s_ann[harg][3], 1.f);
        float t5[5];
        t5[0] = ((s_ann[harg][0] - acx) / aw) * 10.f;
        t5[1] = ((s_ann[harg][1] - acy) / ah) * 10.f;
        t5[2] = __logf(gw / aw) * 5.f;
        t5[3] = __logf(gh / ah) * 5.f;
        t5[4] = ((s_ann[harg][4] - ath) * PI_180) * 10.f;
        const float* rrow = reg + ((size_t)b * A + a) * 5;
#pragma unroll
        for (int k = 0; k < 5; k++) {
            float d = fabsf(t5[k] - rrow[k]);
            rsum += (d <= (1.f / 9.f)) ? 4.5f * d * d : (d - (0.5f / 9.f));
        }
    }

    closs *= LN2F;

    // ---- block reduction ----
    unsigned fullm = 0xffffffffu;
#pragma unroll
    for (int o = 16; o > 0; o >>= 1) {
        closs += __shfl_down_sync(fullm, closs, o);
        rsum  += __shfl_down_sync(fullm, rsum,  o);
        isPos += __shfl_down_sync(fullm, isPos, o);
    }
    __shared__ float red_c[8];
    __shared__ float red_r[8];
    __shared__ float red_p[8];
    if (lane == 0) { red_c[warp] = closs; red_r[warp] = rsum; red_p[warp] = isPos; }
    __syncthreads();

    __shared__ unsigned s_isLast;
    const int nblk = gridDim.x;
    if (threadIdx.x == 0) {
        float tc = 0.f, tr = 0.f, tp = 0.f;
        int nw = blockDim.x >> 5;
        for (int w = 0; w < nw; w++) { tc += red_c[w]; tr += red_r[w]; tp += red_p[w]; }
        int pidx = b * nblk + blockIdx.x;
        g_pc[pidx] = tc;
        g_pr[pidx] = tr;
        g_pn[pidx] = tp;
        __threadfence();
        unsigned total = gridDim.x * gridDim.y;
        unsigned old = atomicAdd(&g_count, 1u);
        s_isLast = (old == total - 1u) ? 1u : 0u;
    }
    __syncthreads();

    if (s_isLast) {
        const int B = gridDim.y;
        int w = warp;
        __shared__ float s_c[8], s_r[8];
        if (w < B) {
            float tc = 0.f, tr = 0.f, tp = 0.f;
            for (int i = lane; i < nblk; i += 32) {
                tc += __ldcg(&g_pc[w * nblk + i]);
                tr += __ldcg(&g_pr[w * nblk + i]);
                tp += __ldcg(&g_pn[w * nblk + i]);
            }
#pragma unroll
            for (int o = 16; o > 0; o >>= 1) {
                tc += __shfl_down_sync(0xffffffffu, tc, o);
                tr += __shfl_down_sync(0xffffffffu, tr, o);
                tp += __shfl_down_sync(0xffffffffu, tp, o);
            }
            if (lane == 0) {
                s_c[w] = tc / fmaxf(tp, 1.f);
                s_r[w] = (tp > 0.f) ? (tr / fmaxf(tp * 5.f, 1.f)) : 0.f;
            }
        }
        __syncthreads();
        if (threadIdx.x == 0) {
            float cm = 0.f, rm = 0.f;
            for (int bb = 0; bb < B; bb++) { cm += s_c[bb]; rm += s_r[bb]; }
            out[0] = cm / (float)B;
            out[1] = rm / (float)B;
            g_count = 0;
        }
    }
}

extern "C" void kernel_launch(void* const* d_in, const int* in_sizes, int n_in,
                              void* d_out, int out_size) {
    const float* cls  = (const float*)d_in[0];
    const float* reg  = (const float*)d_in[1];
    const float* anch = (const float*)d_in[2];
    const float* ann  = (const float*)d_in[3];
    float* out = (float*)d_out;

    int A  = in_sizes[2] / 5;
    int B  = in_sizes[1] / (A * 5);
    int NC = in_sizes[0] / (B * A);
    int M  = in_sizes[3] / (B * 6);
    if (M > MAXM) M = MAXM;

    int nblk = (A + 255) / 256;
    dim3 grid(nblk, B);
    if (M == 32 && NC == 15) {
        focal_main_kernel<32, 15><<<grid, 256>>>(cls, reg, anch, ann, out, A, NC, M);
    } else {
        focal_main_kernel<0, 0><<<grid, 256>>>(cls, reg, anch, ann, out, A, NC, M);
    }
}